// round 1
// baseline (speedup 1.0000x reference)
#include <cuda_runtime.h>
#include <math_constants.h>

#define Bq 4
#define Hh 12
#define Ss 2048
#define Dd 64
#define BM 128
#define BN 64

__global__ __launch_bounds__(128, 3)
void sdp_flash_fp32(const float* __restrict__ Q, const float* __restrict__ K,
                    const float* __restrict__ V, float* __restrict__ O) {
    __shared__ float Ks[BN][Dd];
    __shared__ float Vs[BN][Dd];

    const int qtile = blockIdx.x;
    const int bh    = blockIdx.y;          // b*H + h
    const int b     = bh / Hh;
    const int h     = bh % Hh;
    const int tid   = threadIdx.x;

    const float scale = 0.03608439182435161f;   // 1/sqrt(768)

    const int m_row = qtile * BM + tid;
    const float* qptr = Q + ((size_t)bh * Ss + m_row) * Dd;

    float q[Dd];
    #pragma unroll
    for (int d = 0; d < Dd; d += 4) {
        float4 v4 = *(const float4*)(qptr + d);
        q[d]   = v4.x * scale;
        q[d+1] = v4.y * scale;
        q[d+2] = v4.z * scale;
        q[d+3] = v4.w * scale;
    }

    float acc[Dd];
    #pragma unroll
    for (int d = 0; d < Dd; d++) acc[d] = 0.f;
    float m_run = -CUDART_INF_F;
    float l_run = 0.f;

    const float* kbase = K + (size_t)bh * Ss * Dd;
    const float* vbase = V + ((size_t)b * Ss * Hh + h) * Dd;   // + k*H*D per row

    for (int kt = 0; kt < Ss; kt += BN) {
        // --- stage K tile (coalesced, contiguous rows) ---
        const float4* ksrc = (const float4*)(kbase + (size_t)kt * Dd);
        #pragma unroll
        for (int i = 0; i < (BN * Dd / 4) / 128; i++) {
            int idx = tid + i * 128;
            ((float4*)&Ks[0][0])[idx] = ksrc[idx];
        }
        // --- stage V tile (rows strided by H*D in gmem) ---
        #pragma unroll
        for (int i = 0; i < (BN * Dd / 4) / 128; i++) {
            int idx = tid + i * 128;
            int row = idx >> 4;      // idx / (D/4)
            int col = idx & 15;
            ((float4*)&Vs[0][0])[idx] =
                *(const float4*)(vbase + (size_t)(kt + row) * (Hh * Dd) + col * 4);
        }
        __syncthreads();

        for (int k = 0; k < BN; k++) {
            // ---- score: dot(q, K[k]) with 4 independent accumulator chains ----
            float s0 = 0.f, s1 = 0.f, s2 = 0.f, s3 = 0.f;
            #pragma unroll
            for (int d = 0; d < Dd; d += 4) {
                float4 kv = *(const float4*)&Ks[k][d];   // broadcast LDS.128
                s0 += q[d]   * kv.x;
                s1 += q[d+1] * kv.y;
                s2 += q[d+2] * kv.z;
                s3 += q[d+3] * kv.w;
            }
            float s = (s0 + s1) + (s2 + s3);

            // ---- online softmax, rescale only on new max ----
            if (s > m_run) {
                float c = __expf(m_run - s);   // 0 on first hit (m_run = -inf)
                l_run *= c;
                #pragma unroll
                for (int d = 0; d < Dd; d++) acc[d] *= c;
                m_run = s;
            }
            float p = __expf(s - m_run);
            l_run += p;

            // ---- PV accumulate ----
            #pragma unroll
            for (int d = 0; d < Dd; d += 4) {
                float4 vv = *(const float4*)&Vs[k][d];   // broadcast LDS.128
                acc[d]   += p * vv.x;
                acc[d+1] += p * vv.y;
                acc[d+2] += p * vv.z;
                acc[d+3] += p * vv.w;
            }
        }
        __syncthreads();
    }

    const float inv_l = 1.0f / l_run;
    float* optr = O + ((size_t)bh * Ss + m_row) * Dd;
    #pragma unroll
    for (int d = 0; d < Dd; d += 4) {
        float4 o4;
        o4.x = acc[d]   * inv_l;
        o4.y = acc[d+1] * inv_l;
        o4.z = acc[d+2] * inv_l;
        o4.w = acc[d+3] * inv_l;
        *(float4*)(optr + d) = o4;
    }
}

extern "C" void kernel_launch(void* const* d_in, const int* in_sizes, int n_in,
                              void* d_out, int out_size) {
    const float* Q = (const float*)d_in[0];
    const float* K = (const float*)d_in[1];
    const float* V = (const float*)d_in[2];
    float* O = (float*)d_out;

    dim3 grid(Ss / BM, Bq * Hh);   // (16, 48) = 768 CTAs
    dim3 block(128);
    sdp_flash_fp32<<<grid, block>>>(Q, K, V, O);
}